// round 1
// baseline (speedup 1.0000x reference)
#include <cuda_runtime.h>
#include <math.h>

// Problem constants
#define TT 64
#define BB 48
#define EE 400
#define HH 1152
#define G4 4608          // 4*H
#define VV 32000
#define MM (TT * BB)     // 3072
#define DEC_ELEMS 98304000   // MM * VV
#define SH 165888            // 3 * BB * HH

// ---------------- scratch (device globals; no cudaMalloc allowed) ----------------
__device__ float g_emb[MM * EE];      // [3072, 400]
__device__ float g_pre[MM * G4];      // [3072, 4608] input-projection preacts for current layer
__device__ float g_seqA[MM * HH];     // layer output sequences (ping)
__device__ float g_seqB[MM * HH];     // (pong)
__device__ float g_hA[3 * BB * HH];   // h state ping
__device__ float g_hB[3 * BB * HH];   // h state pong
__device__ float g_c [3 * BB * HH];   // c state (thread-owned, in-place)

// ---------------- init: copy h0/c0 into state buffers ----------------
__global__ void init_state(const float* __restrict__ h0, const float* __restrict__ c0) {
    int i = blockIdx.x * 256 + threadIdx.x;
    if (i < SH) {
        g_hA[i] = h0[i];
        g_c[i]  = c0[i];
    }
}

// ---------------- embedding gather: g_emb[row] = emb_W[x[row]] ----------------
__global__ void embed_k(const int* __restrict__ x, const float* __restrict__ embW) {
    int row = blockIdx.x;                   // row = t*B + b, matches x[T,B] flat order
    int tok = x[row];
    const float4* src = (const float4*)(embW + (size_t)tok * EE);
    float4* dst = (float4*)(g_emb + (size_t)row * EE);
    for (int i = threadIdx.x; i < EE / 4; i += blockDim.x) dst[i] = src[i];
}

// ---------------- SGEMM (NT): C[M,N] = A[M,K] * W[N,K]^T + bias1 (+bias2) ----------------
// 128x128 tile, BK=8, 256 threads, 8x8 per-thread register tile.
// asel: 0 -> g_emb, 1 -> g_seqA, 2 -> g_seqB.  Cext==nullptr -> g_pre.
__global__ __launch_bounds__(256, 2)
void sgemm_nt(int asel, const float* __restrict__ Wt, float* __restrict__ Cext,
              const float* __restrict__ bias1, const float* __restrict__ bias2,
              int Ndim, int K)
{
    const float* A = (asel == 0) ? g_emb : (asel == 1 ? g_seqA : g_seqB);
    float* C = Cext ? Cext : g_pre;

    __shared__ float As[8][128];
    __shared__ float Bs[8][128];

    const int tid = threadIdx.x;
    const int tx = tid & 15;        // 0..15 -> n sub-tile
    const int ty = tid >> 4;        // 0..15 -> m sub-tile
    const int mt = blockIdx.x;
    const int nt = blockIdx.y;

    const float* Ab = A  + (size_t)mt * 128 * K;
    const float* Bb = Wt + (size_t)nt * 128 * K;

    const int lrow = tid >> 1;           // 0..127
    const int lcol = (tid & 1) << 2;     // 0 or 4

    float acc[8][8];
#pragma unroll
    for (int i = 0; i < 8; i++)
#pragma unroll
        for (int j = 0; j < 8; j++) acc[i][j] = 0.f;

    for (int k0 = 0; k0 < K; k0 += 8) {
        float4 av = *(const float4*)(Ab + (size_t)lrow * K + k0 + lcol);
        float4 bv = *(const float4*)(Bb + (size_t)lrow * K + k0 + lcol);
        As[lcol + 0][lrow] = av.x; As[lcol + 1][lrow] = av.y;
        As[lcol + 2][lrow] = av.z; As[lcol + 3][lrow] = av.w;
        Bs[lcol + 0][lrow] = bv.x; Bs[lcol + 1][lrow] = bv.y;
        Bs[lcol + 2][lrow] = bv.z; Bs[lcol + 3][lrow] = bv.w;
        __syncthreads();
#pragma unroll
        for (int kk = 0; kk < 8; kk++) {
            float a[8], b[8];
            *(float4*)(a)     = *(const float4*)(&As[kk][ty * 8]);
            *(float4*)(a + 4) = *(const float4*)(&As[kk][ty * 8 + 4]);
            *(float4*)(b)     = *(const float4*)(&Bs[kk][tx * 8]);
            *(float4*)(b + 4) = *(const float4*)(&Bs[kk][tx * 8 + 4]);
#pragma unroll
            for (int i = 0; i < 8; i++)
#pragma unroll
                for (int j = 0; j < 8; j++)
                    acc[i][j] = fmaf(a[i], b[j], acc[i][j]);
        }
        __syncthreads();
    }

    const int ncol0 = nt * 128 + tx * 8;
    float bcol[8];
#pragma unroll
    for (int j = 0; j < 8; j++) {
        float bb = bias1[ncol0 + j];
        if (bias2) bb += bias2[ncol0 + j];
        bcol[j] = bb;
    }
#pragma unroll
    for (int i = 0; i < 8; i++) {
        const int m = mt * 128 + ty * 8 + i;
        float4 v0, v1;
        v0.x = acc[i][0] + bcol[0]; v0.y = acc[i][1] + bcol[1];
        v0.z = acc[i][2] + bcol[2]; v0.w = acc[i][3] + bcol[3];
        v1.x = acc[i][4] + bcol[4]; v1.y = acc[i][5] + bcol[5];
        v1.z = acc[i][6] + bcol[6]; v1.w = acc[i][7] + bcol[7];
        *(float4*)(&C[(size_t)m * Ndim + ncol0])     = v0;
        *(float4*)(&C[(size_t)m * Ndim + ncol0 + 4]) = v1;
    }
}

// ---------------- fused LSTM recurrent step ----------------
// grid = 144 CTAs (each owns 8 H-columns across all 4 gates), 256 threads.
// Computes p = pre[t] + h_in @ Wh^T for its 48x32 slice, then the cell update.
__global__ __launch_bounds__(256)
void lstm_step(const float* __restrict__ Wh, int t, int layer, int ysel)
{
    __shared__ float hsm[48 * 64];

    const int tid = threadIdx.x;
    const int col = tid & 31;      // 0..31: gate-group(4) x jo(8)
    const int bg  = tid >> 5;      // 0..7: batch group
    const int g32 = col >> 3;      // gate index 0..3 (i,f,o,g)
    const int jo  = col & 7;
    const int s   = blockIdx.x;    // H-slice: columns s*8 .. s*8+7
    const int n   = g32 * HH + s * 8 + jo;   // preact column in [0,4608)

    const float* base_in = ((t & 1) ? g_hB : g_hA) + (size_t)layer * BB * HH;
    float* base_out      = ((t & 1) ? g_hA : g_hB) + (size_t)layer * BB * HH;
    float* cst           = g_c + (size_t)layer * BB * HH;
    const float* pre_t   = g_pre + (size_t)t * BB * G4;
    float* y_out         = (ysel ? g_seqB : g_seqA) + (size_t)t * BB * HH;

    const float* wrow = Wh + (size_t)n * HH;

    float4 acc[6];
#pragma unroll
    for (int bi = 0; bi < 6; bi++) acc[bi] = make_float4(0.f, 0.f, 0.f, 0.f);

    for (int k0 = 0; k0 < HH; k0 += 64) {
        __syncthreads();   // protect hsm from previous iteration's readers
#pragma unroll
        for (int r = 0; r < 12; r++) {
            int i = tid + r * 256;                 // 48*64 / 256 = 12
            hsm[i] = base_in[(i >> 6) * HH + k0 + (i & 63)];
        }
        __syncthreads();

        float4 w[16];
#pragma unroll
        for (int q = 0; q < 16; q++) w[q] = *(const float4*)(wrow + k0 + q * 4);

#pragma unroll
        for (int q = 0; q < 16; q++) {
#pragma unroll
            for (int bi = 0; bi < 6; bi++) {
                float4 hv = *(const float4*)(hsm + (bg + 8 * bi) * 64 + q * 4);
                acc[bi].x = fmaf(w[q].x, hv.x, acc[bi].x);
                acc[bi].y = fmaf(w[q].y, hv.y, acc[bi].y);
                acc[bi].z = fmaf(w[q].z, hv.z, acc[bi].z);
                acc[bi].w = fmaf(w[q].w, hv.w, acc[bi].w);
            }
        }
    }

#pragma unroll
    for (int bi = 0; bi < 6; bi++) {
        const int b = bg + 8 * bi;
        float p = pre_t[(size_t)b * G4 + n]
                + ((acc[bi].x + acc[bi].y) + (acc[bi].z + acc[bi].w));
        // gather the 4 gates for column jo from lanes jo, jo+8, jo+16, jo+24
        float iv = __shfl_sync(0xffffffffu, p, jo,      32);
        float fv = __shfl_sync(0xffffffffu, p, jo + 8,  32);
        float ov = __shfl_sync(0xffffffffu, p, jo + 16, 32);
        float gv = __shfl_sync(0xffffffffu, p, jo + 24, 32);
        if (col < 8) {
            const int j = s * 8 + col;
            float ig = 1.f / (1.f + __expf(-iv));
            float fg = 1.f / (1.f + __expf(-fv));
            float og = 1.f / (1.f + __expf(-ov));
            float gg = tanhf(gv);
            float cn = fg * cst[b * HH + j] + ig * gg;
            float hn = og * tanhf(cn);
            cst[b * HH + j]      = cn;
            base_out[b * HH + j] = hn;
            y_out[b * HH + j]    = hn;
        }
    }
}

// ---------------- copy final states into output tail ----------------
__global__ void finalize(float* __restrict__ out) {
    int i = blockIdx.x * 256 + threadIdx.x;
    if (i < SH) {
        out[DEC_ELEMS + i]      = g_hA[i];   // 64 steps: ping-pong ends in A
        out[DEC_ELEMS + SH + i] = g_c[i];
    }
}

extern "C" void kernel_launch(void* const* d_in, const int* in_sizes, int n_in,
                              void* d_out, int out_size)
{
    (void)in_sizes; (void)n_in; (void)out_size;
    const int*   x     = (const int*)d_in[0];
    const float* h0    = (const float*)d_in[1];
    const float* c0    = (const float*)d_in[2];
    const float* embW  = (const float*)d_in[3];
    const float* W_i0  = (const float*)d_in[4];
    const float* b_i0  = (const float*)d_in[5];
    const float* W_h0  = (const float*)d_in[6];
    const float* b_h0  = (const float*)d_in[7];
    const float* W_i1  = (const float*)d_in[8];
    const float* b_i1  = (const float*)d_in[9];
    const float* W_h1  = (const float*)d_in[10];
    const float* b_h1  = (const float*)d_in[11];
    const float* W_i2  = (const float*)d_in[12];
    const float* b_i2  = (const float*)d_in[13];
    const float* W_h2  = (const float*)d_in[14];
    const float* b_h2  = (const float*)d_in[15];
    const float* W_dec = (const float*)d_in[16];
    const float* b_dec = (const float*)d_in[17];
    float* out = (float*)d_out;

    init_state<<<648, 256>>>(h0, c0);
    embed_k<<<3072, 128>>>(x, embW);

    // ---- layer 0: input proj over all T, then 64 recurrent steps ----
    sgemm_nt<<<dim3(24, 36), 256>>>(0, W_i0, nullptr, b_i0, b_h0, G4, EE);
    for (int t = 0; t < TT; t++) lstm_step<<<144, 256>>>(W_h0, t, 0, 0);

    // ---- layer 1 ----
    sgemm_nt<<<dim3(24, 36), 256>>>(1, W_i1, nullptr, b_i1, b_h1, G4, HH);
    for (int t = 0; t < TT; t++) lstm_step<<<144, 256>>>(W_h1, t, 1, 1);

    // ---- layer 2 ----
    sgemm_nt<<<dim3(24, 36), 256>>>(2, W_i2, nullptr, b_i2, b_h2, G4, HH);
    for (int t = 0; t < TT; t++) lstm_step<<<144, 256>>>(W_h2, t, 2, 0);

    // ---- decoder: [3072,1152] x [1152,32000]^T + b_dec -> d_out ----
    sgemm_nt<<<dim3(24, 250), 256>>>(1, W_dec, out, b_dec, nullptr, VV, HH);

    finalize<<<648, 256>>>(out);
}

// round 2
// speedup vs baseline: 1.4902x; 1.4902x over previous
#include <cuda_runtime.h>
#include <math.h>

// Problem constants
#define TT 64
#define BB 48
#define EE 400
#define HH 1152
#define G4 4608          // 4*H
#define VV 32000
#define MM (TT * BB)     // 3072
#define DEC_ELEMS 98304000   // MM * VV
#define SH 165888            // 3 * BB * HH
#define NCTA 144

// SMEM layout constants for the persistent LSTM kernel
#define WS_STRIDE 1156            // 1152 + 4 pad (stride % 32 == 4 -> conflict-free LDS.128)
#define WS_FLOATS (32 * WS_STRIDE)
#define HS_FLOATS (48 * 64)       // one h chunk
#define LSTM_SMEM ((WS_FLOATS + 2 * HS_FLOATS) * 4)

// ---------------- scratch (device globals; no cudaMalloc allowed) ----------------
__device__ float g_emb[MM * EE];      // [3072, 400]
__device__ float g_pre[MM * G4];      // [3072, 4608] input-projection preacts for current layer
__device__ float g_seqA[MM * HH];     // layer output sequences (ping)
__device__ float g_seqB[MM * HH];     // (pong)
__device__ float g_hA[3 * BB * HH];   // h state ping
__device__ float g_hB[3 * BB * HH];   // h state pong
__device__ float g_c [3 * BB * HH];   // c state (thread-owned, in-place)
__device__ int   g_bar;               // grid barrier counter (monotone within one launch set)

// ---------------- init: copy h0/c0 into state buffers, reset barrier ----------------
__global__ void init_state(const float* __restrict__ h0, const float* __restrict__ c0) {
    int i = blockIdx.x * 256 + threadIdx.x;
    if (i == 0) g_bar = 0;
    if (i < SH) {
        g_hA[i] = h0[i];
        g_c[i]  = c0[i];
    }
}

// ---------------- embedding gather: g_emb[row] = emb_W[x[row]] ----------------
__global__ void embed_k(const int* __restrict__ x, const float* __restrict__ embW) {
    int row = blockIdx.x;                   // row = t*B + b, matches x[T,B] flat order
    int tok = x[row];
    const float4* src = (const float4*)(embW + (size_t)tok * EE);
    float4* dst = (float4*)(g_emb + (size_t)row * EE);
    for (int i = threadIdx.x; i < EE / 4; i += blockDim.x) dst[i] = src[i];
}

// ---------------- SGEMM (NT): C[M,N] = A[M,K] * W[N,K]^T + bias1 (+bias2) ----------------
// 128x128 tile, BK=8, 256 threads, 8x8 per-thread register tile.
// asel: 0 -> g_emb, 1 -> g_seqA, 2 -> g_seqB.  Cext==nullptr -> g_pre.
__global__ __launch_bounds__(256, 2)
void sgemm_nt(int asel, const float* __restrict__ Wt, float* __restrict__ Cext,
              const float* __restrict__ bias1, const float* __restrict__ bias2,
              int Ndim, int K)
{
    const float* A = (asel == 0) ? g_emb : (asel == 1 ? g_seqA : g_seqB);
    float* C = Cext ? Cext : g_pre;

    __shared__ float As[8][128];
    __shared__ float Bs[8][128];

    const int tid = threadIdx.x;
    const int tx = tid & 15;        // 0..15 -> n sub-tile
    const int ty = tid >> 4;        // 0..15 -> m sub-tile
    const int mt = blockIdx.x;
    const int nt = blockIdx.y;

    const float* Ab = A  + (size_t)mt * 128 * K;
    const float* Bb = Wt + (size_t)nt * 128 * K;

    const int lrow = tid >> 1;           // 0..127
    const int lcol = (tid & 1) << 2;     // 0 or 4

    float acc[8][8];
#pragma unroll
    for (int i = 0; i < 8; i++)
#pragma unroll
        for (int j = 0; j < 8; j++) acc[i][j] = 0.f;

    for (int k0 = 0; k0 < K; k0 += 8) {
        float4 av = *(const float4*)(Ab + (size_t)lrow * K + k0 + lcol);
        float4 bv = *(const float4*)(Bb + (size_t)lrow * K + k0 + lcol);
        As[lcol + 0][lrow] = av.x; As[lcol + 1][lrow] = av.y;
        As[lcol + 2][lrow] = av.z; As[lcol + 3][lrow] = av.w;
        Bs[lcol + 0][lrow] = bv.x; Bs[lcol + 1][lrow] = bv.y;
        Bs[lcol + 2][lrow] = bv.z; Bs[lcol + 3][lrow] = bv.w;
        __syncthreads();
#pragma unroll
        for (int kk = 0; kk < 8; kk++) {
            float a[8], b[8];
            *(float4*)(a)     = *(const float4*)(&As[kk][ty * 8]);
            *(float4*)(a + 4) = *(const float4*)(&As[kk][ty * 8 + 4]);
            *(float4*)(b)     = *(const float4*)(&Bs[kk][tx * 8]);
            *(float4*)(b + 4) = *(const float4*)(&Bs[kk][tx * 8 + 4]);
#pragma unroll
            for (int i = 0; i < 8; i++)
#pragma unroll
                for (int j = 0; j < 8; j++)
                    acc[i][j] = fmaf(a[i], b[j], acc[i][j]);
        }
        __syncthreads();
    }

    const int ncol0 = nt * 128 + tx * 8;
    float bcol[8];
#pragma unroll
    for (int j = 0; j < 8; j++) {
        float bb = bias1[ncol0 + j];
        if (bias2) bb += bias2[ncol0 + j];
        bcol[j] = bb;
    }
#pragma unroll
    for (int i = 0; i < 8; i++) {
        const int m = mt * 128 + ty * 8 + i;
        float4 v0, v1;
        v0.x = acc[i][0] + bcol[0]; v0.y = acc[i][1] + bcol[1];
        v0.z = acc[i][2] + bcol[2]; v0.w = acc[i][3] + bcol[3];
        v1.x = acc[i][4] + bcol[4]; v1.y = acc[i][5] + bcol[5];
        v1.z = acc[i][6] + bcol[6]; v1.w = acc[i][7] + bcol[7];
        *(float4*)(&C[(size_t)m * Ndim + ncol0])     = v0;
        *(float4*)(&C[(size_t)m * Ndim + ncol0 + 4]) = v1;
    }
}

// ---------------- persistent per-layer LSTM kernel ----------------
// 144 CTAs x 256 threads, all co-resident. CTA s owns preact columns
// n = g*1152 + s*8 + jo (g=0..3 gates, jo=0..7), i.e. H-columns s*8..s*8+7.
// Its 32 Wh rows (147KB) live in SMEM for all 64 timesteps. h is staged
// per-64k-chunk into double-buffered SMEM. Steps are separated by a
// software grid barrier on g_bar (monotone target; reset by init_state).
__global__ void __launch_bounds__(256, 1)
lstm_layer(const float* __restrict__ Wh, int layer, int ysel, int bar_base)
{
    extern __shared__ float smem[];
    float* W_s = smem;                  // [32][WS_STRIDE]
    float* hs  = smem + WS_FLOATS;      // [2][48][64]

    const int tid  = threadIdx.x;
    const int col  = tid & 31;          // lane = local preact column 0..31
    const int warp = tid >> 5;          // warp = batch group (6 batches)
    const int g32  = col >> 3;
    const int jo   = col & 7;
    const int s    = blockIdx.x;
    const int n    = g32 * HH + s * 8 + jo;

    // ---- load this CTA's 32 Wh rows into SMEM (once per layer) ----
    for (int idx = tid; idx < 32 * 288; idx += 256) {
        int r = idx / 288, q = idx - r * 288;          // r = local row, q = float4 idx
        int nn = (r >> 3) * HH + s * 8 + (r & 7);
        float4 v = *(const float4*)(Wh + (size_t)nn * HH + q * 4);
        *(float4*)(&W_s[r * WS_STRIDE + q * 4]) = v;
    }
    __syncthreads();

    float* cst = g_c + (size_t)layer * BB * HH;

    for (int t = 0; t < TT; ++t) {
        const float* hin  = ((t & 1) ? g_hB : g_hA) + (size_t)layer * BB * HH;
        float* hout       = ((t & 1) ? g_hA : g_hB) + (size_t)layer * BB * HH;
        const float* pre_t = g_pre + (size_t)t * BB * G4;
        float* y_out      = (ysel ? g_seqB : g_seqA) + (size_t)t * BB * HH;

        // ---- stage chunk 0 of h ----
#pragma unroll
        for (int it = 0; it < 3; it++) {
            int i = tid + it * 256;
            int b = i >> 4, off = (i & 15) << 2;
            *(float4*)&hs[b * 64 + off] = *(const float4*)(hin + (size_t)b * HH + off);
        }
        __syncthreads();

        float4 acc[6];
#pragma unroll
        for (int bi = 0; bi < 6; bi++) acc[bi] = make_float4(0.f, 0.f, 0.f, 0.f);

        for (int c = 0; c < 18; ++c) {
            const int cb = c & 1;
            // prefetch next h chunk into registers (overlaps with compute)
            float4 pf[3];
            if (c < 17) {
                const int k0n = (c + 1) * 64;
#pragma unroll
                for (int it = 0; it < 3; it++) {
                    int i = tid + it * 256;
                    int b = i >> 4, off = (i & 15) << 2;
                    pf[it] = *(const float4*)(hin + (size_t)b * HH + k0n + off);
                }
            }

            const float* wbase = &W_s[col * WS_STRIDE + c * 64];
            const float* hbase = &hs[cb * HS_FLOATS + warp * 6 * 64];
#pragma unroll
            for (int q = 0; q < 16; ++q) {
                float4 w4 = *(const float4*)(wbase + q * 4);
#pragma unroll
                for (int bi = 0; bi < 6; ++bi) {
                    float4 h4 = *(const float4*)(hbase + bi * 64 + q * 4);  // warp-uniform -> broadcast
                    acc[bi].x = fmaf(w4.x, h4.x, acc[bi].x);
                    acc[bi].y = fmaf(w4.y, h4.y, acc[bi].y);
                    acc[bi].z = fmaf(w4.z, h4.z, acc[bi].z);
                    acc[bi].w = fmaf(w4.w, h4.w, acc[bi].w);
                }
            }

            if (c < 17) {
                // all threads have finished reading buf (c-1)&1 == (c+1)&1 (they passed
                // the sync at end of iteration c-1), so the STS below is safe.
#pragma unroll
                for (int it = 0; it < 3; it++) {
                    int i = tid + it * 256;
                    int b = i >> 4, off = (i & 15) << 2;
                    *(float4*)&hs[(cb ^ 1) * HS_FLOATS + b * 64 + off] = pf[it];
                }
                __syncthreads();   // publish buf (c+1)&1 before chunk c+1 compute
            }
        }

        // ---- epilogue: add input-proj preact, gate nonlinearities, state update ----
#pragma unroll
        for (int bi = 0; bi < 6; bi++) {
            const int b = warp * 6 + bi;
            float p = pre_t[(size_t)b * G4 + n]
                    + ((acc[bi].x + acc[bi].y) + (acc[bi].z + acc[bi].w));
            float iv = __shfl_sync(0xffffffffu, p, jo,      32);
            float fv = __shfl_sync(0xffffffffu, p, jo + 8,  32);
            float ov = __shfl_sync(0xffffffffu, p, jo + 16, 32);
            float gv = __shfl_sync(0xffffffffu, p, jo + 24, 32);
            if (col < 8) {
                const int j = s * 8 + col;
                float ig = 1.f / (1.f + __expf(-iv));
                float fg = 1.f / (1.f + __expf(-fv));
                float og = 1.f / (1.f + __expf(-ov));
                float gg = tanhf(gv);
                float cn = fg * cst[b * HH + j] + ig * gg;
                float hn = og * tanhf(cn);
                cst[b * HH + j]    = cn;
                hout[b * HH + j]   = hn;
                y_out[(size_t)b * HH + j] = hn;
            }
        }

        // ---- grid barrier: all CTAs must finish step t before step t+1 ----
        __threadfence();
        __syncthreads();
        if (tid == 0) {
            atomicAdd(&g_bar, 1);
            const int target = bar_base + (t + 1) * NCTA;
            while (atomicAdd(&g_bar, 0) < target) __nanosleep(64);
            __threadfence();
        }
        __syncthreads();
    }
}

// ---------------- copy final states into output tail ----------------
__global__ void finalize(float* __restrict__ out) {
    int i = blockIdx.x * 256 + threadIdx.x;
    if (i < SH) {
        out[DEC_ELEMS + i]      = g_hA[i];   // 64 steps: ping-pong ends in A
        out[DEC_ELEMS + SH + i] = g_c[i];
    }
}

extern "C" void kernel_launch(void* const* d_in, const int* in_sizes, int n_in,
                              void* d_out, int out_size)
{
    (void)in_sizes; (void)n_in; (void)out_size;
    const int*   x     = (const int*)d_in[0];
    const float* h0    = (const float*)d_in[1];
    const float* c0    = (const float*)d_in[2];
    const float* embW  = (const float*)d_in[3];
    const float* W_i0  = (const float*)d_in[4];
    const float* b_i0  = (const float*)d_in[5];
    const float* W_h0  = (const float*)d_in[6];
    const float* b_h0  = (const float*)d_in[7];
    const float* W_i1  = (const float*)d_in[8];
    const float* b_i1  = (const float*)d_in[9];
    const float* W_h1  = (const float*)d_in[10];
    const float* b_h1  = (const float*)d_in[11];
    const float* W_i2  = (const float*)d_in[12];
    const float* b_i2  = (const float*)d_in[13];
    const float* W_h2  = (const float*)d_in[14];
    const float* b_h2  = (const float*)d_in[15];
    const float* W_dec = (const float*)d_in[16];
    const float* b_dec = (const float*)d_in[17];
    float* out = (float*)d_out;

    static int smem_set = 0;
    if (!smem_set) {
        cudaFuncSetAttribute(lstm_layer, cudaFuncAttributeMaxDynamicSharedMemorySize, LSTM_SMEM);
        smem_set = 1;
    }

    init_state<<<648, 256>>>(h0, c0);
    embed_k<<<3072, 128>>>(x, embW);

    // ---- layer 0: input proj over all T, then persistent 64-step recurrence ----
    sgemm_nt<<<dim3(24, 36), 256>>>(0, W_i0, nullptr, b_i0, b_h0, G4, EE);
    lstm_layer<<<NCTA, 256, LSTM_SMEM>>>(W_h0, 0, 0, 0 * TT * NCTA);

    // ---- layer 1 ----
    sgemm_nt<<<dim3(24, 36), 256>>>(1, W_i1, nullptr, b_i1, b_h1, G4, HH);
    lstm_layer<<<NCTA, 256, LSTM_SMEM>>>(W_h1, 1, 1, 1 * TT * NCTA);

    // ---- layer 2 ----
    sgemm_nt<<<dim3(24, 36), 256>>>(2, W_i2, nullptr, b_i2, b_h2, G4, HH);
    lstm_layer<<<NCTA, 256, LSTM_SMEM>>>(W_h2, 2, 0, 2 * TT * NCTA);

    // ---- decoder: [3072,1152] x [1152,32000]^T + b_dec -> d_out ----
    sgemm_nt<<<dim3(24, 250), 256>>>(1, W_dec, out, b_dec, nullptr, VV, HH);

    finalize<<<648, 256>>>(out);
}

// round 3
// speedup vs baseline: 2.2459x; 1.5071x over previous
#include <cuda_runtime.h>
#include <math.h>
#include <stdint.h>

// Problem constants
#define TT 64
#define BB 48
#define EE 400
#define HH 1152
#define G4 4608          // 4*H
#define VV 32000
#define MM (TT * BB)     // 3072
#define DEC_ELEMS 98304000   // MM * VV
#define SH 165888            // 3 * BB * HH
#define NCTA 144

// SMEM layout constants for the persistent LSTM kernel
#define WS_STRIDE 1156            // 1152 + 4 pad
#define WS_FLOATS (32 * WS_STRIDE)
#define HS_FLOATS (48 * 64)       // one h chunk
#define LSTM_SMEM ((WS_FLOATS + 2 * HS_FLOATS) * 4)

// SMEM for tf32 GEMM: A 2 stages of [256][20] + B 2 stages of [128][20]
#define AS_STAGE (256 * 20)
#define BS_STAGE (128 * 20)
#define GEMM_SMEM ((2 * AS_STAGE + 2 * BS_STAGE) * 4)   // 61440 B

// ---------------- scratch (device globals; no cudaMalloc allowed) ----------------
__device__ float g_emb[MM * EE];      // [3072, 400]
__device__ float g_pre[MM * G4];      // [3072, 4608]
__device__ float g_seqA[MM * HH];
__device__ float g_seqB[MM * HH];
__device__ float g_hA[3 * BB * HH];
__device__ float g_hB[3 * BB * HH];
__device__ float g_c [3 * BB * HH];
__device__ int   g_bar;

// ---------------- init ----------------
__global__ void init_state(const float* __restrict__ h0, const float* __restrict__ c0) {
    int i = blockIdx.x * 256 + threadIdx.x;
    if (i == 0) g_bar = 0;
    if (i < SH) {
        g_hA[i] = h0[i];
        g_c[i]  = c0[i];
    }
}

// ---------------- embedding gather ----------------
__global__ void embed_k(const int* __restrict__ x, const float* __restrict__ embW) {
    int row = blockIdx.x;
    int tok = x[row];
    const float4* src = (const float4*)(embW + (size_t)tok * EE);
    float4* dst = (float4*)(g_emb + (size_t)row * EE);
    for (int i = threadIdx.x; i < EE / 4; i += blockDim.x) dst[i] = src[i];
}

// ---------------- tf32 helpers ----------------
__device__ __forceinline__ float to_tf32(float x) {
    uint32_t u;
    asm("cvt.rna.tf32.f32 %0, %1;" : "=r"(u) : "f"(x));
    return __uint_as_float(u);
}

__device__ __forceinline__ void mma_tf32(float4& c, const uint32_t* a, const uint32_t* b) {
    asm volatile(
        "mma.sync.aligned.m16n8k8.row.col.f32.tf32.tf32.f32 "
        "{%0,%1,%2,%3}, {%4,%5,%6,%7}, {%8,%9}, {%0,%1,%2,%3};\n"
        : "+f"(c.x), "+f"(c.y), "+f"(c.z), "+f"(c.w)
        : "r"(a[0]), "r"(a[1]), "r"(a[2]), "r"(a[3]), "r"(b[0]), "r"(b[1]));
}

// ---------------- tf32 tensor-core GEMM (NT): C[M,N] = A[M,K] * W[N,K]^T + bias ----------------
// CTA tile 256(m) x 128(n), BK=16, 256 threads = 8 warps as 4(m) x 2(n), warp tile 64x64.
// asel: 0 -> g_emb, 1 -> g_seqA, 2 -> g_seqB.  Cext==nullptr -> g_pre.
__global__ void __launch_bounds__(256, 1)
gemm_tf32(int asel, const float* __restrict__ Wt, float* __restrict__ Cext,
          const float* __restrict__ bias1, const float* __restrict__ bias2,
          int Ndim, int K)
{
    const float* A = (asel == 0) ? g_emb : (asel == 1 ? g_seqA : g_seqB);
    float* C = Cext ? Cext : g_pre;

    extern __shared__ float sm[];
    float* As = sm;                     // [2][256][20]
    float* Bs = sm + 2 * AS_STAGE;      // [2][128][20]

    const int tid  = threadIdx.x;
    const int lane = tid & 31;
    const int wid  = tid >> 5;
    const int wm   = wid >> 1;          // 0..3
    const int wn   = wid & 1;           // 0..1
    const int g    = lane >> 2;         // 0..7
    const int t4   = lane & 3;          // 0..3

    const float* Ab = A  + (size_t)(blockIdx.x * 256) * K;
    const float* Bb = Wt + (size_t)(blockIdx.y * 128) * K;

    const int la_m = tid >> 2;          // 0..63
    const int la_k = (tid & 3) * 4;     // float4 k offset within BK

    float4 c[4][8];
#pragma unroll
    for (int i = 0; i < 4; i++)
#pragma unroll
        for (int j = 0; j < 8; j++) c[i][j] = make_float4(0.f, 0.f, 0.f, 0.f);

    const int NK = K / 16;

    // prefetch k-iter 0
    float4 av[4], bv[2];
#pragma unroll
    for (int r = 0; r < 4; r++)
        av[r] = *(const float4*)(Ab + (size_t)(la_m + 64 * r) * K + la_k);
#pragma unroll
    for (int r = 0; r < 2; r++)
        bv[r] = *(const float4*)(Bb + (size_t)(la_m + 64 * r) * K + la_k);

    // store stage 0
    {
        float* Ad = As;
        float* Bd = Bs;
#pragma unroll
        for (int r = 0; r < 4; r++) {
            float4 w = make_float4(to_tf32(av[r].x), to_tf32(av[r].y), to_tf32(av[r].z), to_tf32(av[r].w));
            *(float4*)(Ad + (la_m + 64 * r) * 20 + la_k) = w;
        }
#pragma unroll
        for (int r = 0; r < 2; r++) {
            float4 w = make_float4(to_tf32(bv[r].x), to_tf32(bv[r].y), to_tf32(bv[r].z), to_tf32(bv[r].w));
            *(float4*)(Bd + (la_m + 64 * r) * 20 + la_k) = w;
        }
    }

    for (int kt = 0; kt < NK; ++kt) {
        __syncthreads();   // stage kt&1 published

        // prefetch next k-iter
        if (kt + 1 < NK) {
            const int k0 = (kt + 1) * 16;
#pragma unroll
            for (int r = 0; r < 4; r++)
                av[r] = *(const float4*)(Ab + (size_t)(la_m + 64 * r) * K + k0 + la_k);
#pragma unroll
            for (int r = 0; r < 2; r++)
                bv[r] = *(const float4*)(Bb + (size_t)(la_m + 64 * r) * K + k0 + la_k);
        }

        // compute on stage kt&1
        const float* Aw = As + (kt & 1) * AS_STAGE + (wm * 64) * 20;
        const float* Bw = Bs + (kt & 1) * BS_STAGE + (wn * 64) * 20;
#pragma unroll
        for (int ks = 0; ks < 2; ks++) {
            const int kk = ks * 8 + t4;
            uint32_t a[4][4], b[8][2];
#pragma unroll
            for (int mt = 0; mt < 4; mt++) {
                const int base = (mt * 16 + g) * 20;
                a[mt][0] = __float_as_uint(Aw[base + kk]);
                a[mt][1] = __float_as_uint(Aw[base + 160 + kk]);       // +8 rows
                a[mt][2] = __float_as_uint(Aw[base + kk + 4]);
                a[mt][3] = __float_as_uint(Aw[base + 160 + kk + 4]);
            }
#pragma unroll
            for (int nt = 0; nt < 8; nt++) {
                const int nb = (nt * 8 + g) * 20;
                b[nt][0] = __float_as_uint(Bw[nb + kk]);
                b[nt][1] = __float_as_uint(Bw[nb + kk + 4]);
            }
#pragma unroll
            for (int mt = 0; mt < 4; mt++)
#pragma unroll
                for (int nt = 0; nt < 8; nt++)
                    mma_tf32(c[mt][nt], a[mt], b[nt]);
        }

        // store next stage
        if (kt + 1 < NK) {
            float* Ad = As + ((kt + 1) & 1) * AS_STAGE;
            float* Bd = Bs + ((kt + 1) & 1) * BS_STAGE;
#pragma unroll
            for (int r = 0; r < 4; r++) {
                float4 w = make_float4(to_tf32(av[r].x), to_tf32(av[r].y), to_tf32(av[r].z), to_tf32(av[r].w));
                *(float4*)(Ad + (la_m + 64 * r) * 20 + la_k) = w;
            }
#pragma unroll
            for (int r = 0; r < 2; r++) {
                float4 w = make_float4(to_tf32(bv[r].x), to_tf32(bv[r].y), to_tf32(bv[r].z), to_tf32(bv[r].w));
                *(float4*)(Bd + (la_m + 64 * r) * 20 + la_k) = w;
            }
        }
    }

    // ---- epilogue: bias add + store ----
#pragma unroll
    for (int nt = 0; nt < 8; nt++) {
        const int cn = blockIdx.y * 128 + wn * 64 + nt * 8 + 2 * t4;
        float bb0 = bias1[cn], bb1 = bias1[cn + 1];
        if (bias2) { bb0 += bias2[cn]; bb1 += bias2[cn + 1]; }
#pragma unroll
        for (int mt = 0; mt < 4; mt++) {
            const int rm = blockIdx.x * 256 + wm * 64 + mt * 16 + g;
            float2 v0 = make_float2(c[mt][nt].x + bb0, c[mt][nt].y + bb1);
            float2 v1 = make_float2(c[mt][nt].z + bb0, c[mt][nt].w + bb1);
            *(float2*)(C + (size_t)rm * Ndim + cn)       = v0;
            *(float2*)(C + (size_t)(rm + 8) * Ndim + cn) = v1;
        }
    }
}

// ---------------- persistent per-layer LSTM kernel (unchanged from R2) ----------------
__global__ void __launch_bounds__(256, 1)
lstm_layer(const float* __restrict__ Wh, int layer, int ysel, int bar_base)
{
    extern __shared__ float smem[];
    float* W_s = smem;                  // [32][WS_STRIDE]
    float* hs  = smem + WS_FLOATS;      // [2][48][64]

    const int tid  = threadIdx.x;
    const int col  = tid & 31;
    const int warp = tid >> 5;
    const int g32  = col >> 3;
    const int jo   = col & 7;
    const int s    = blockIdx.x;
    const int n    = g32 * HH + s * 8 + jo;

    for (int idx = tid; idx < 32 * 288; idx += 256) {
        int r = idx / 288, q = idx - r * 288;
        int nn = (r >> 3) * HH + s * 8 + (r & 7);
        float4 v = *(const float4*)(Wh + (size_t)nn * HH + q * 4);
        *(float4*)(&W_s[r * WS_STRIDE + q * 4]) = v;
    }
    __syncthreads();

    float* cst = g_c + (size_t)layer * BB * HH;

    for (int t = 0; t < TT; ++t) {
        const float* hin   = ((t & 1) ? g_hB : g_hA) + (size_t)layer * BB * HH;
        float* hout        = ((t & 1) ? g_hA : g_hB) + (size_t)layer * BB * HH;
        const float* pre_t = g_pre + (size_t)t * BB * G4;
        float* y_out       = (ysel ? g_seqB : g_seqA) + (size_t)t * BB * HH;

#pragma unroll
        for (int it = 0; it < 3; it++) {
            int i = tid + it * 256;
            int b = i >> 4, off = (i & 15) << 2;
            *(float4*)&hs[b * 64 + off] = *(const float4*)(hin + (size_t)b * HH + off);
        }
        __syncthreads();

        float4 acc[6];
#pragma unroll
        for (int bi = 0; bi < 6; bi++) acc[bi] = make_float4(0.f, 0.f, 0.f, 0.f);

        for (int c = 0; c < 18; ++c) {
            const int cb = c & 1;
            float4 pf[3];
            if (c < 17) {
                const int k0n = (c + 1) * 64;
#pragma unroll
                for (int it = 0; it < 3; it++) {
                    int i = tid + it * 256;
                    int b = i >> 4, off = (i & 15) << 2;
                    pf[it] = *(const float4*)(hin + (size_t)b * HH + k0n + off);
                }
            }

            const float* wbase = &W_s[col * WS_STRIDE + c * 64];
            const float* hbase = &hs[cb * HS_FLOATS + warp * 6 * 64];
#pragma unroll
            for (int q = 0; q < 16; ++q) {
                float4 w4 = *(const float4*)(wbase + q * 4);
#pragma unroll
                for (int bi = 0; bi < 6; ++bi) {
                    float4 h4 = *(const float4*)(hbase + bi * 64 + q * 4);
                    acc[bi].x = fmaf(w4.x, h4.x, acc[bi].x);
                    acc[bi].y = fmaf(w4.y, h4.y, acc[bi].y);
                    acc[bi].z = fmaf(w4.z, h4.z, acc[bi].z);
                    acc[bi].w = fmaf(w4.w, h4.w, acc[bi].w);
                }
            }

            if (c < 17) {
#pragma unroll
                for (int it = 0; it < 3; it++) {
                    int i = tid + it * 256;
                    int b = i >> 4, off = (i & 15) << 2;
                    *(float4*)&hs[(cb ^ 1) * HS_FLOATS + b * 64 + off] = pf[it];
                }
                __syncthreads();
            }
        }

#pragma unroll
        for (int bi = 0; bi < 6; bi++) {
            const int b = warp * 6 + bi;
            float p = pre_t[(size_t)b * G4 + n]
                    + ((acc[bi].x + acc[bi].y) + (acc[bi].z + acc[bi].w));
            float iv = __shfl_sync(0xffffffffu, p, jo,      32);
            float fv = __shfl_sync(0xffffffffu, p, jo + 8,  32);
            float ov = __shfl_sync(0xffffffffu, p, jo + 16, 32);
            float gv = __shfl_sync(0xffffffffu, p, jo + 24, 32);
            if (col < 8) {
                const int j = s * 8 + col;
                float ig = 1.f / (1.f + __expf(-iv));
                float fg = 1.f / (1.f + __expf(-fv));
                float og = 1.f / (1.f + __expf(-ov));
                float gg = tanhf(gv);
                float cn = fg * cst[b * HH + j] + ig * gg;
                float hn = og * tanhf(cn);
                cst[b * HH + j]    = cn;
                hout[b * HH + j]   = hn;
                y_out[(size_t)b * HH + j] = hn;
            }
        }

        __threadfence();
        __syncthreads();
        if (tid == 0) {
            atomicAdd(&g_bar, 1);
            const int target = bar_base + (t + 1) * NCTA;
            while (atomicAdd(&g_bar, 0) < target) __nanosleep(64);
            __threadfence();
        }
        __syncthreads();
    }
}

// ---------------- copy final states into output tail ----------------
__global__ void finalize(float* __restrict__ out) {
    int i = blockIdx.x * 256 + threadIdx.x;
    if (i < SH) {
        out[DEC_ELEMS + i]      = g_hA[i];
        out[DEC_ELEMS + SH + i] = g_c[i];
    }
}

extern "C" void kernel_launch(void* const* d_in, const int* in_sizes, int n_in,
                              void* d_out, int out_size)
{
    (void)in_sizes; (void)n_in; (void)out_size;
    const int*   x     = (const int*)d_in[0];
    const float* h0    = (const float*)d_in[1];
    const float* c0    = (const float*)d_in[2];
    const float* embW  = (const float*)d_in[3];
    const float* W_i0  = (const float*)d_in[4];
    const float* b_i0  = (const float*)d_in[5];
    const float* W_h0  = (const float*)d_in[6];
    const float* b_h0  = (const float*)d_in[7];
    const float* W_i1  = (const float*)d_in[8];
    const float* b_i1  = (const float*)d_in[9];
    const float* W_h1  = (const float*)d_in[10];
    const float* b_h1  = (const float*)d_in[11];
    const float* W_i2  = (const float*)d_in[12];
    const float* b_i2  = (const float*)d_in[13];
    const float* W_h2  = (const float*)d_in[14];
    const float* b_h2  = (const float*)d_in[15];
    const float* W_dec = (const float*)d_in[16];
    const float* b_dec = (const float*)d_in[17];
    float* out = (float*)d_out;

    static int attr_set = 0;
    if (!attr_set) {
        cudaFuncSetAttribute(lstm_layer, cudaFuncAttributeMaxDynamicSharedMemorySize, LSTM_SMEM);
        cudaFuncSetAttribute(gemm_tf32, cudaFuncAttributeMaxDynamicSharedMemorySize, GEMM_SMEM);
        attr_set = 1;
    }

    init_state<<<648, 256>>>(h0, c0);
    embed_k<<<3072, 128>>>(x, embW);

    // ---- layer 0 ----
    gemm_tf32<<<dim3(12, 36), 256, GEMM_SMEM>>>(0, W_i0, nullptr, b_i0, b_h0, G4, EE);
    lstm_layer<<<NCTA, 256, LSTM_SMEM>>>(W_h0, 0, 0, 0 * TT * NCTA);

    // ---- layer 1 ----
    gemm_tf32<<<dim3(12, 36), 256, GEMM_SMEM>>>(1, W_i1, nullptr, b_i1, b_h1, G4, HH);
    lstm_layer<<<NCTA, 256, LSTM_SMEM>>>(W_h1, 1, 1, 1 * TT * NCTA);

    // ---- layer 2 ----
    gemm_tf32<<<dim3(12, 36), 256, GEMM_SMEM>>>(2, W_i2, nullptr, b_i2, b_h2, G4, HH);
    lstm_layer<<<NCTA, 256, LSTM_SMEM>>>(W_h2, 2, 0, 2 * TT * NCTA);

    // ---- decoder ----
    gemm_tf32<<<dim3(12, 250), 256, GEMM_SMEM>>>(1, W_dec, out, b_dec, nullptr, VV, HH);

    finalize<<<648, 256>>>(out);
}

// round 4
// speedup vs baseline: 2.8640x; 1.2752x over previous
#include <cuda_runtime.h>
#include <math.h>
#include <stdint.h>

// Problem constants
#define TT 64
#define BB 48
#define EE 400
#define HH 1152
#define G4 4608          // 4*H
#define VV 32000
#define MM (TT * BB)     // 3072
#define DEC_ELEMS 98304000   // MM * VV
#define SH 165888            // 3 * BB * HH
#define NCTA 144

// SMEM layout constants for the persistent LSTM kernel
#define WS_STRIDE 1156            // 1152 + 4 pad (stride%32==4 -> conflict-free frag LDS)
#define WS_FLOATS (32 * WS_STRIDE)        // 36992
#define HS_STR 132                        // 128 + 4 pad
#define HS_BUF (48 * HS_STR)              // 6336 floats per buffer
#define PRE_STR 50                        // [32 cols][48 batch + pad]
#define PRE_FLOATS (32 * PRE_STR)         // 1600
#define LSTM_SMEM ((WS_FLOATS + 2 * HS_BUF + 4 * PRE_FLOATS) * 4)   // 224256 B

// SMEM for tf32 GEMM: A 2 stages of [256][20] + B 2 stages of [128][20]
#define AS_STAGE (256 * 20)
#define BS_STAGE (128 * 20)
#define GEMM_SMEM ((2 * AS_STAGE + 2 * BS_STAGE) * 4)   // 61440 B

// ---------------- scratch (device globals; no cudaMalloc allowed) ----------------
__device__ float g_emb[MM * EE];
__device__ float g_pre[MM * G4];
__device__ float g_seqA[MM * HH];
__device__ float g_seqB[MM * HH];
__device__ float g_hA[3 * BB * HH];
__device__ float g_hB[3 * BB * HH];
__device__ float g_c [3 * BB * HH];
__device__ int   g_bar;

// ---------------- init ----------------
__global__ void init_state(const float* __restrict__ h0, const float* __restrict__ c0) {
    int i = blockIdx.x * 256 + threadIdx.x;
    if (i == 0) g_bar = 0;
    if (i < SH) {
        g_hA[i] = h0[i];
        g_c[i]  = c0[i];
    }
}

// ---------------- embedding gather ----------------
__global__ void embed_k(const int* __restrict__ x, const float* __restrict__ embW) {
    int row = blockIdx.x;
    int tok = x[row];
    const float4* src = (const float4*)(embW + (size_t)tok * EE);
    float4* dst = (float4*)(g_emb + (size_t)row * EE);
    for (int i = threadIdx.x; i < EE / 4; i += blockDim.x) dst[i] = src[i];
}

// ---------------- tf32 helpers ----------------
__device__ __forceinline__ float to_tf32(float x) {
    uint32_t u;
    asm("cvt.rna.tf32.f32 %0, %1;" : "=r"(u) : "f"(x));
    return __uint_as_float(u);
}

__device__ __forceinline__ void mma_tf32(float4& c, const uint32_t* a, const uint32_t* b) {
    asm volatile(
        "mma.sync.aligned.m16n8k8.row.col.f32.tf32.tf32.f32 "
        "{%0,%1,%2,%3}, {%4,%5,%6,%7}, {%8,%9}, {%0,%1,%2,%3};\n"
        : "+f"(c.x), "+f"(c.y), "+f"(c.z), "+f"(c.w)
        : "r"(a[0]), "r"(a[1]), "r"(a[2]), "r"(a[3]), "r"(b[0]), "r"(b[1]));
}

// ---------------- tf32 tensor-core GEMM (NT), unchanged from R3 ----------------
__global__ void __launch_bounds__(256, 1)
gemm_tf32(int asel, const float* __restrict__ Wt, float* __restrict__ Cext,
          const float* __restrict__ bias1, const float* __restrict__ bias2,
          int Ndim, int K)
{
    const float* A = (asel == 0) ? g_emb : (asel == 1 ? g_seqA : g_seqB);
    float* C = Cext ? Cext : g_pre;

    extern __shared__ float sm[];
    float* As = sm;
    float* Bs = sm + 2 * AS_STAGE;

    const int tid  = threadIdx.x;
    const int lane = tid & 31;
    const int wid  = tid >> 5;
    const int wm   = wid >> 1;
    const int wn   = wid & 1;
    const int g    = lane >> 2;
    const int t4   = lane & 3;

    const float* Ab = A  + (size_t)(blockIdx.x * 256) * K;
    const float* Bb = Wt + (size_t)(blockIdx.y * 128) * K;

    const int la_m = tid >> 2;
    const int la_k = (tid & 3) * 4;

    float4 c[4][8];
#pragma unroll
    for (int i = 0; i < 4; i++)
#pragma unroll
        for (int j = 0; j < 8; j++) c[i][j] = make_float4(0.f, 0.f, 0.f, 0.f);

    const int NK = K / 16;

    float4 av[4], bv[2];
#pragma unroll
    for (int r = 0; r < 4; r++)
        av[r] = *(const float4*)(Ab + (size_t)(la_m + 64 * r) * K + la_k);
#pragma unroll
    for (int r = 0; r < 2; r++)
        bv[r] = *(const float4*)(Bb + (size_t)(la_m + 64 * r) * K + la_k);

    {
#pragma unroll
        for (int r = 0; r < 4; r++) {
            float4 w = make_float4(to_tf32(av[r].x), to_tf32(av[r].y), to_tf32(av[r].z), to_tf32(av[r].w));
            *(float4*)(As + (la_m + 64 * r) * 20 + la_k) = w;
        }
#pragma unroll
        for (int r = 0; r < 2; r++) {
            float4 w = make_float4(to_tf32(bv[r].x), to_tf32(bv[r].y), to_tf32(bv[r].z), to_tf32(bv[r].w));
            *(float4*)(Bs + (la_m + 64 * r) * 20 + la_k) = w;
        }
    }

    for (int kt = 0; kt < NK; ++kt) {
        __syncthreads();

        if (kt + 1 < NK) {
            const int k0 = (kt + 1) * 16;
#pragma unroll
            for (int r = 0; r < 4; r++)
                av[r] = *(const float4*)(Ab + (size_t)(la_m + 64 * r) * K + k0 + la_k);
#pragma unroll
            for (int r = 0; r < 2; r++)
                bv[r] = *(const float4*)(Bb + (size_t)(la_m + 64 * r) * K + k0 + la_k);
        }

        const float* Aw = As + (kt & 1) * AS_STAGE + (wm * 64) * 20;
        const float* Bw = Bs + (kt & 1) * BS_STAGE + (wn * 64) * 20;
#pragma unroll
        for (int ks = 0; ks < 2; ks++) {
            const int kk = ks * 8 + t4;
            uint32_t a[4][4], b[8][2];
#pragma unroll
            for (int mt = 0; mt < 4; mt++) {
                const int base = (mt * 16 + g) * 20;
                a[mt][0] = __float_as_uint(Aw[base + kk]);
                a[mt][1] = __float_as_uint(Aw[base + 160 + kk]);
                a[mt][2] = __float_as_uint(Aw[base + kk + 4]);
                a[mt][3] = __float_as_uint(Aw[base + 160 + kk + 4]);
            }
#pragma unroll
            for (int nt = 0; nt < 8; nt++) {
                const int nb = (nt * 8 + g) * 20;
                b[nt][0] = __float_as_uint(Bw[nb + kk]);
                b[nt][1] = __float_as_uint(Bw[nb + kk + 4]);
            }
#pragma unroll
            for (int mt = 0; mt < 4; mt++)
#pragma unroll
                for (int nt = 0; nt < 8; nt++)
                    mma_tf32(c[mt][nt], a[mt], b[nt]);
        }

        if (kt + 1 < NK) {
            float* Ad = As + ((kt + 1) & 1) * AS_STAGE;
            float* Bd = Bs + ((kt + 1) & 1) * BS_STAGE;
#pragma unroll
            for (int r = 0; r < 4; r++) {
                float4 w = make_float4(to_tf32(av[r].x), to_tf32(av[r].y), to_tf32(av[r].z), to_tf32(av[r].w));
                *(float4*)(Ad + (la_m + 64 * r) * 20 + la_k) = w;
            }
#pragma unroll
            for (int r = 0; r < 2; r++) {
                float4 w = make_float4(to_tf32(bv[r].x), to_tf32(bv[r].y), to_tf32(bv[r].z), to_tf32(bv[r].w));
                *(float4*)(Bd + (la_m + 64 * r) * 20 + la_k) = w;
            }
        }
    }

#pragma unroll
    for (int nt = 0; nt < 8; nt++) {
        const int cn = blockIdx.y * 128 + wn * 64 + nt * 8 + 2 * t4;
        float bb0 = bias1[cn], bb1 = bias1[cn + 1];
        if (bias2) { bb0 += bias2[cn]; bb1 += bias2[cn + 1]; }
#pragma unroll
        for (int mt = 0; mt < 4; mt++) {
            const int rm = blockIdx.x * 256 + wm * 64 + mt * 16 + g;
            float2 v0 = make_float2(c[mt][nt].x + bb0, c[mt][nt].y + bb1);
            float2 v1 = make_float2(c[mt][nt].z + bb0, c[mt][nt].w + bb1);
            *(float2*)(C + (size_t)rm * Ndim + cn)       = v0;
            *(float2*)(C + (size_t)(rm + 8) * Ndim + cn) = v1;
        }
    }
}

// ---------------- persistent per-layer LSTM kernel, tensor-core version ----------------
// 144 CTAs x 256 threads. CTA s owns 32 preact columns (local col = gate*8+jo,
// global n = gate*HH + s*8 + jo). Wh rows live in SMEM as tf32 for the whole layer.
// mma orientation: M = local col (2 m16 tiles), N = batch (6 n8 tiles), K = 1152.
// 8 warps = 2 batch-halves (nh) x 4 K-quarters-within-chunk (kq).
// h double-buffered in SMEM per 128-k chunk; partials reduced via SMEM scratch.
__global__ void __launch_bounds__(256, 1)
lstm_layer(const float* __restrict__ Wh, int layer, int ysel, int bar_base)
{
    extern __shared__ float smem[];
    float* W_s  = smem;                              // [32][1156] tf32
    float* hs   = smem + WS_FLOATS;                  // [2][48][132] tf32
    float* pres = smem + WS_FLOATS + 2 * HS_BUF;     // [32][50] final preacts
    float* scr  = pres + PRE_FLOATS;                 // 3 x [32][50] partials

    const int tid  = threadIdx.x;
    const int lane = tid & 31;
    const int wid  = tid >> 5;
    const int g    = lane >> 2;        // 0..7
    const int t4   = lane & 3;         // 0..3
    const int nh   = wid & 1;          // batch half
    const int kq   = wid >> 1;         // k-quarter within chunk
    const int s    = blockIdx.x;

    // ---- load this CTA's 32 Wh rows into SMEM as tf32 (once per layer) ----
    for (int idx = tid; idx < 32 * 288; idx += 256) {
        int r = idx / 288, q = idx - r * 288;
        int nn = (r >> 3) * HH + s * 8 + (r & 7);
        float4 v = *(const float4*)(Wh + (size_t)nn * HH + q * 4);
        v.x = to_tf32(v.x); v.y = to_tf32(v.y); v.z = to_tf32(v.z); v.w = to_tf32(v.w);
        *(float4*)(&W_s[r * WS_STRIDE + q * 4]) = v;
    }
    __syncthreads();

    float* cst = g_c + (size_t)layer * BB * HH;

    for (int t = 0; t < TT; ++t) {
        const float* hin   = ((t & 1) ? g_hB : g_hA) + (size_t)layer * BB * HH;
        float* hout        = ((t & 1) ? g_hA : g_hB) + (size_t)layer * BB * HH;
        const float* pre_t = g_pre + (size_t)t * BB * G4;
        float* y_out       = (ysel ? g_seqB : g_seqA) + (size_t)t * BB * HH;

        // ---- stage chunk 0 (tf32) ----
#pragma unroll
        for (int it = 0; it < 6; it++) {
            int i = tid + it * 256;
            int row = i >> 5, off = (i & 31) << 2;
            float4 v = *(const float4*)(hin + (size_t)row * HH + off);
            v.x = to_tf32(v.x); v.y = to_tf32(v.y); v.z = to_tf32(v.z); v.w = to_tf32(v.w);
            *(float4*)&hs[row * HS_STR + off] = v;
        }
        __syncthreads();

        float4 acc[6];     // [mt*3 + nt]
#pragma unroll
        for (int i = 0; i < 6; i++) acc[i] = make_float4(0.f, 0.f, 0.f, 0.f);

        for (int c = 0; c < 9; ++c) {
            const int cb = c & 1;

            // prefetch next chunk into registers
            float4 pf[6];
            if (c < 8) {
                const int k0n = (c + 1) * 128;
#pragma unroll
                for (int it = 0; it < 6; it++) {
                    int i = tid + it * 256;
                    int row = i >> 5, off = (i & 31) << 2;
                    pf[it] = *(const float4*)(hin + (size_t)row * HH + k0n + off);
                }
            }

            // compute this warp's 4 k8-steps of the chunk
            const int kbw = c * 128 + kq * 32;          // global k base (for W_s)
            const int kbh = cb * HS_BUF + kq * 32;      // hs base
#pragma unroll
            for (int ks = 0; ks < 4; ks++) {
                const int kw = kbw + ks * 8 + t4;
                const int kh = kbh + ks * 8 + t4;
                uint32_t a[2][4], b[3][2];
#pragma unroll
                for (int mt = 0; mt < 2; mt++) {
                    const float* wr = &W_s[(mt * 16 + g) * WS_STRIDE + kw];
                    a[mt][0] = __float_as_uint(wr[0]);
                    a[mt][1] = __float_as_uint(wr[8 * WS_STRIDE]);
                    a[mt][2] = __float_as_uint(wr[4]);
                    a[mt][3] = __float_as_uint(wr[8 * WS_STRIDE + 4]);
                }
#pragma unroll
                for (int nt = 0; nt < 3; nt++) {
                    const float* hr = &hs[kh + (nh * 24 + nt * 8 + g) * HS_STR];
                    b[nt][0] = __float_as_uint(hr[0]);
                    b[nt][1] = __float_as_uint(hr[4]);
                }
#pragma unroll
                for (int mt = 0; mt < 2; mt++)
#pragma unroll
                    for (int nt = 0; nt < 3; nt++)
                        mma_tf32(acc[mt * 3 + nt], a[mt], b[nt]);
            }

            if (c < 8) {
#pragma unroll
                for (int it = 0; it < 6; it++) {
                    int i = tid + it * 256;
                    int row = i >> 5, off = (i & 31) << 2;
                    float4 v = pf[it];
                    v.x = to_tf32(v.x); v.y = to_tf32(v.y); v.z = to_tf32(v.z); v.w = to_tf32(v.w);
                    *(float4*)&hs[(cb ^ 1) * HS_BUF + row * HS_STR + off] = v;
                }
                __syncthreads();
            }
        }

        // ---- k-quarter reduction: kq!=0 write partials, kq==0 combines ----
        if (kq != 0) {
            float* dst = scr + (kq - 1) * PRE_FLOATS;
#pragma unroll
            for (int mt = 0; mt < 2; mt++)
#pragma unroll
                for (int nt = 0; nt < 3; nt++) {
                    const float4 v = acc[mt * 3 + nt];
                    const int m = mt * 16 + g;
                    const int n = nh * 24 + nt * 8 + 2 * t4;
                    *(float2*)&dst[m * PRE_STR + n]       = make_float2(v.x, v.y);
                    *(float2*)&dst[(m + 8) * PRE_STR + n] = make_float2(v.z, v.w);
                }
        }
        __syncthreads();
        if (kq == 0) {
#pragma unroll
            for (int mt = 0; mt < 2; mt++)
#pragma unroll
                for (int nt = 0; nt < 3; nt++) {
                    const float4 v = acc[mt * 3 + nt];
                    const int m = mt * 16 + g;
                    const int n = nh * 24 + nt * 8 + 2 * t4;
                    float2 lo = make_float2(v.x, v.y);
                    float2 hi = make_float2(v.z, v.w);
#pragma unroll
                    for (int r = 0; r < 3; r++) {
                        float2 a0 = *(const float2*)&scr[r * PRE_FLOATS + m * PRE_STR + n];
                        float2 a1 = *(const float2*)&scr[r * PRE_FLOATS + (m + 8) * PRE_STR + n];
                        lo.x += a0.x; lo.y += a0.y;
                        hi.x += a1.x; hi.y += a1.y;
                    }
                    *(float2*)&pres[m * PRE_STR + n]       = lo;
                    *(float2*)&pres[(m + 8) * PRE_STR + n] = hi;
                }
        }
        __syncthreads();

        // ---- cell update: 384 (batch, jo) items ----
#pragma unroll
        for (int rep = 0; rep < 2; rep++) {
            int idx = tid + rep * 256;
            if (idx < 384) {
                const int b  = idx >> 3;
                const int jo = idx & 7;
                const float* pt = pre_t + (size_t)b * G4 + s * 8 + jo;
                float iv = pres[(jo)      * PRE_STR + b] + pt[0];
                float fv = pres[(8 + jo)  * PRE_STR + b] + pt[HH];
                float ov = pres[(16 + jo) * PRE_STR + b] + pt[2 * HH];
                float gv = pres[(24 + jo) * PRE_STR + b] + pt[3 * HH];
                const int j = s * 8 + jo;
                float ig = 1.f / (1.f + __expf(-iv));
                float fg = 1.f / (1.f + __expf(-fv));
                float og = 1.f / (1.f + __expf(-ov));
                float gg = tanhf(gv);
                float cn = fg * cst[b * HH + j] + ig * gg;
                float hn = og * tanhf(cn);
                cst[b * HH + j]           = cn;
                hout[b * HH + j]          = hn;
                y_out[(size_t)b * HH + j] = hn;
            }
        }

        // ---- grid barrier ----
        __threadfence();
        __syncthreads();
        if (tid == 0) {
            atomicAdd(&g_bar, 1);
            const int target = bar_base + (t + 1) * NCTA;
            while (atomicAdd(&g_bar, 0) < target) __nanosleep(64);
            __threadfence();
        }
        __syncthreads();
    }
}

// ---------------- copy final states into output tail ----------------
__global__ void finalize(float* __restrict__ out) {
    int i = blockIdx.x * 256 + threadIdx.x;
    if (i < SH) {
        out[DEC_ELEMS + i]      = g_hA[i];
        out[DEC_ELEMS + SH + i] = g_c[i];
    }
}

extern "C" void kernel_launch(void* const* d_in, const int* in_sizes, int n_in,
                              void* d_out, int out_size)
{
    (void)in_sizes; (void)n_in; (void)out_size;
    const int*   x     = (const int*)d_in[0];
    const float* h0    = (const float*)d_in[1];
    const float* c0    = (const float*)d_in[2];
    const float* embW  = (const float*)d_in[3];
    const float* W_i0  = (const float*)d_in[4];
    const float* b_i0  = (const float*)d_in[5];
    const float* W_h0  = (const float*)d_in[6];
    const float* b_h0  = (const float*)d_in[7];
    const float* W_i1  = (const float*)d_in[8];
    const float* b_i1  = (const float*)d_in[9];
    const float* W_h1  = (const float*)d_in[10];
    const float* b_h1  = (const float*)d_in[11];
    const float* W_i2  = (const float*)d_in[12];
    const float* b_i2  = (const float*)d_in[13];
    const float* W_h2  = (const float*)d_in[14];
    const float* b_h2  = (const float*)d_in[15];
    const float* W_dec = (const float*)d_in[16];
    const float* b_dec = (const float*)d_in[17];
    float* out = (float*)d_out;

    static int attr_set = 0;
    if (!attr_set) {
        cudaFuncSetAttribute(lstm_layer, cudaFuncAttributeMaxDynamicSharedMemorySize, LSTM_SMEM);
        cudaFuncSetAttribute(gemm_tf32, cudaFuncAttributeMaxDynamicSharedMemorySize, GEMM_SMEM);
        attr_set = 1;
    }

    init_state<<<648, 256>>>(h0, c0);
    embed_k<<<3072, 128>>>(x, embW);

    // ---- layer 0 ----
    gemm_tf32<<<dim3(12, 36), 256, GEMM_SMEM>>>(0, W_i0, nullptr, b_i0, b_h0, G4, EE);
    lstm_layer<<<NCTA, 256, LSTM_SMEM>>>(W_h0, 0, 0, 0 * TT * NCTA);

    // ---- layer 1 ----
    gemm_tf32<<<dim3(12, 36), 256, GEMM_SMEM>>>(1, W_i1, nullptr, b_i1, b_h1, G4, HH);
    lstm_layer<<<NCTA, 256, LSTM_SMEM>>>(W_h1, 1, 1, 1 * TT * NCTA);

    // ---- layer 2 ----
    gemm_tf32<<<dim3(12, 36), 256, GEMM_SMEM>>>(2, W_i2, nullptr, b_i2, b_h2, G4, HH);
    lstm_layer<<<NCTA, 256, LSTM_SMEM>>>(W_h2, 2, 0, 2 * TT * NCTA);

    // ---- decoder ----
    gemm_tf32<<<dim3(12, 250), 256, GEMM_SMEM>>>(1, W_dec, out, b_dec, nullptr, VV, HH);

    finalize<<<648, 256>>>(out);
}